// round 4
// baseline (speedup 1.0000x reference)
#include <cuda_runtime.h>
#include <math.h>

#define NN 50000
#define EE 600000
#define CC 128
#define KK 128
#define SCAN_BLOCKS ((NN + 255) / 256)   // 196

// Scratch (static device globals; no runtime allocation allowed)
__device__ float g_out[(size_t)NN * CC];       // softplus(h@W0+b0)
__device__ float g_P[(size_t)NN * 512];        // [pi_f | pi_s | pj_f | pj_s] per node
__device__ float g_aggr[(size_t)NN * CC];      // segment-sum result
__device__ float g_stats[2 * CC];              // per-channel sum, sumsq
__device__ float g_Wcat[KK * 512];             // packed [Wf_i|Ws_i|Wf_j|Ws_j]
// CSR scratch
__device__ int   g_deg[NN];
__device__ int   g_roff[NN];
__device__ int   g_cursor[NN];
__device__ int   g_bsum[SCAN_BLOCKS];
__device__ int   g_boff[SCAN_BLOCKS];
__device__ int   g_esrc[EE];                   // src sorted by dst
__device__ float g_ee[EE];                     // e value sorted by dst

__device__ __forceinline__ float sp_f(float x) {
    return x > 20.0f ? x : log1pf(__expf(x));
}
__device__ __forceinline__ float sigm_f(float x) {
    return 1.0f / (1.0f + __expf(-x));
}

// ---------------- weight packing ----------------
__global__ void prep_wcat(const float* __restrict__ Wf, const float* __restrict__ Ws) {
    int idx = blockIdx.x * blockDim.x + threadIdx.x;
    if (idx >= KK * 512) return;
    int k = idx >> 9;
    int c = idx & 511;
    float v;
    if (c < 128)      v = Wf[k * 128 + c];
    else if (c < 256) v = Ws[k * 128 + (c - 128)];
    else if (c < 384) v = Wf[(128 + k) * 128 + (c - 256)];
    else              v = Ws[(128 + k) * 128 + (c - 384)];
    g_Wcat[idx] = v;
}

// ---------------- GEMM (fp32, 128x128 tile, 8x8 microtile) ----------------
template <int ACT>
__global__ void __launch_bounds__(256, 2)
gemm128(const float* __restrict__ A, const float* __restrict__ B,
        const float* __restrict__ bias, float* __restrict__ Co,
        int M, int Nc) {
    __shared__ float As[16][132];
    __shared__ float Bs[16][128];
    int tid = threadIdx.x;
    int tx = tid & 15, ty = tid >> 4;
    int row0 = blockIdx.x * 128, col0 = blockIdx.y * 128;
    float acc[8][8] = {};

    for (int kc = 0; kc < KK; kc += 16) {
#pragma unroll
        for (int l = 0; l < 2; l++) {
            int f = tid + l * 256;
            int m = f >> 2;
            int kq = (f & 3) << 2;
            int gr = row0 + m;
            float4 av = make_float4(0.f, 0.f, 0.f, 0.f);
            if (gr < M) av = *(const float4*)(A + (size_t)gr * KK + kc + kq);
            As[kq + 0][m] = av.x;
            As[kq + 1][m] = av.y;
            As[kq + 2][m] = av.z;
            As[kq + 3][m] = av.w;
        }
#pragma unroll
        for (int l = 0; l < 2; l++) {
            int f = tid + l * 256;
            int k = f >> 5;
            int c4 = (f & 31) << 2;
            *(float4*)&Bs[k][c4] = *(const float4*)(B + (size_t)(kc + k) * Nc + col0 + c4);
        }
        __syncthreads();

#pragma unroll
        for (int k = 0; k < 16; k++) {
            float4 a0 = *(float4*)&As[k][ty * 4];
            float4 a1 = *(float4*)&As[k][64 + ty * 4];
            float4 b0 = *(float4*)&Bs[k][tx * 4];
            float4 b1 = *(float4*)&Bs[k][64 + tx * 4];
            float ar[8] = {a0.x, a0.y, a0.z, a0.w, a1.x, a1.y, a1.z, a1.w};
            float br[8] = {b0.x, b0.y, b0.z, b0.w, b1.x, b1.y, b1.z, b1.w};
#pragma unroll
            for (int i = 0; i < 8; i++)
#pragma unroll
                for (int j = 0; j < 8; j++)
                    acc[i][j] += ar[i] * br[j];
        }
        __syncthreads();
    }

#pragma unroll
    for (int i = 0; i < 8; i++) {
        int gr = row0 + (i < 4 ? ty * 4 + i : 64 + ty * 4 + (i - 4));
        if (gr >= M) continue;
#pragma unroll
        for (int half = 0; half < 2; half++) {
            int gc = col0 + half * 64 + tx * 4;
            float4 v;
            v.x = acc[i][half * 4 + 0];
            v.y = acc[i][half * 4 + 1];
            v.z = acc[i][half * 4 + 2];
            v.w = acc[i][half * 4 + 3];
            if (ACT) {
                v.x = sp_f(v.x + bias[gc + 0]);
                v.y = sp_f(v.y + bias[gc + 1]);
                v.z = sp_f(v.z + bias[gc + 2]);
                v.w = sp_f(v.w + bias[gc + 3]);
            }
            *(float4*)(Co + (size_t)gr * Nc + gc) = v;
        }
    }
}

// ---------------- CSR build ----------------
__global__ void hist(const int* __restrict__ ei) {
    int e = blockIdx.x * blockDim.x + threadIdx.x;
    if (e < EE) atomicAdd(&g_deg[ei[EE + e]], 1);
}

__global__ void scan_local() {
    __shared__ int s[256];
    int tid = threadIdx.x;
    int i = blockIdx.x * 256 + tid;
    int v = (i < NN) ? g_deg[i] : 0;
    s[tid] = v;
    __syncthreads();
#pragma unroll
    for (int off = 1; off < 256; off <<= 1) {
        int t = (tid >= off) ? s[tid - off] : 0;
        __syncthreads();
        s[tid] += t;
        __syncthreads();
    }
    if (i < NN) g_roff[i] = s[tid] - v;     // exclusive
    if (tid == 255) g_bsum[blockIdx.x] = s[255];
}

__global__ void scan_bsums() {
    __shared__ int s[256];
    int tid = threadIdx.x;
    int v = (tid < SCAN_BLOCKS) ? g_bsum[tid] : 0;
    s[tid] = v;
    __syncthreads();
#pragma unroll
    for (int off = 1; off < 256; off <<= 1) {
        int t = (tid >= off) ? s[tid - off] : 0;
        __syncthreads();
        s[tid] += t;
        __syncthreads();
    }
    if (tid < SCAN_BLOCKS) g_boff[tid] = s[tid] - v;   // exclusive
}

__global__ void scan_add() {
    int i = blockIdx.x * 256 + threadIdx.x;
    if (i < NN) {
        int r = g_roff[i] + g_boff[blockIdx.x];
        g_roff[i] = r;
        g_cursor[i] = r;
    }
}

// ---------------- e = softplus(edge_attr @ Wsh + bsh) fused with CSR scatter
// Half-warp per edge: 2 coalesced float4 loads per lane, 4-step reduce,
// lane 0 claims CSR slot and writes (src, e) directly in dst-sorted order.
__global__ void edge_gauss_scatter(const float* __restrict__ ea,
                                   const float* __restrict__ Wsh,
                                   const float* __restrict__ bsh,
                                   const int* __restrict__ ei) {
    int t = blockIdx.x * blockDim.x + threadIdx.x;
    int e = t >> 4;
    if (e >= EE) return;
    int l = t & 15;
    const float* base = ea + (size_t)e * 128;
    float4 a0 = *(const float4*)(base + l * 4);
    float4 a1 = *(const float4*)(base + 64 + l * 4);
    float4 w0 = *(const float4*)(Wsh + l * 4);
    float4 w1 = *(const float4*)(Wsh + 64 + l * 4);
    float d = a0.x * w0.x + a0.y * w0.y + a0.z * w0.z + a0.w * w0.w
            + a1.x * w1.x + a1.y * w1.y + a1.z * w1.z + a1.w * w1.w;
#pragma unroll
    for (int o = 8; o; o >>= 1) d += __shfl_xor_sync(0xFFFFFFFFu, d, o);
    if (l == 0) {
        float ev = sp_f(d + bsh[0]);
        int src = __ldg(ei + e);
        int dst = __ldg(ei + EE + e);
        int pos = atomicAdd(&g_cursor[dst], 1);
        g_esrc[pos] = src;
        g_ee[pos] = ev;
    }
}

// ---------------- CSR edge messages + fused BN stats ----------------
// One warp per dst node (strided). pi parts loaded once per node; inner loop
// unrolled x2 for MLP=4; plain stores to g_aggr; block stats -> red.global.
__global__ void __launch_bounds__(256)
edge_msg_csr(const float* __restrict__ Wf, const float* __restrict__ Ws,
             const float* __restrict__ bf, const float* __restrict__ bs,
             int nwarps) {
    __shared__ float s_stats[2 * CC];
    int tid = threadIdx.x;
    int lane = tid & 31;
    int c = lane * 4;
    s_stats[tid] = 0.0f;
    __syncthreads();

    float4 wfe = *(const float4*)(Wf + 256 * 128 + c);
    float4 wse = *(const float4*)(Ws + 256 * 128 + c);
    float4 bfv = *(const float4*)(bf + c);
    float4 bsv = *(const float4*)(bs + c);

    float lsum[4] = {}, lsq[4] = {};

    int gw = blockIdx.x * 8 + (tid >> 5);
    for (int i = gw; i < NN; i += nwarps) {
        const float4* Pi = (const float4*)(g_P + (size_t)i * 512);
        float4 pif = Pi[lane];
        float4 pis = Pi[32 + lane];
        int k = g_roff[i];
        int end = k + g_deg[i];
        float4 acc = make_float4(0.f, 0.f, 0.f, 0.f);

        // pairs of edges: 4 independent float4 gathers in flight
        for (; k + 2 <= end; k += 2) {
            int s0 = g_esrc[k], s1 = g_esrc[k + 1];
            float e0 = g_ee[k], e1 = g_ee[k + 1];
            const float4* Pj0 = (const float4*)(g_P + (size_t)s0 * 512 + 256);
            const float4* Pj1 = (const float4*)(g_P + (size_t)s1 * 512 + 256);
            float4 f0 = Pj0[lane];
            float4 q0 = Pj0[32 + lane];
            float4 f1 = Pj1[lane];
            float4 q1 = Pj1[32 + lane];
            acc.x += sigm_f(pif.x + f0.x + e0 * wfe.x + bfv.x) * sp_f(pis.x + q0.x + e0 * wse.x + bsv.x);
            acc.y += sigm_f(pif.y + f0.y + e0 * wfe.y + bfv.y) * sp_f(pis.y + q0.y + e0 * wse.y + bsv.y);
            acc.z += sigm_f(pif.z + f0.z + e0 * wfe.z + bfv.z) * sp_f(pis.z + q0.z + e0 * wse.z + bsv.z);
            acc.w += sigm_f(pif.w + f0.w + e0 * wfe.w + bfv.w) * sp_f(pis.w + q0.w + e0 * wse.w + bsv.w);
            acc.x += sigm_f(pif.x + f1.x + e1 * wfe.x + bfv.x) * sp_f(pis.x + q1.x + e1 * wse.x + bsv.x);
            acc.y += sigm_f(pif.y + f1.y + e1 * wfe.y + bfv.y) * sp_f(pis.y + q1.y + e1 * wse.y + bsv.y);
            acc.z += sigm_f(pif.z + f1.z + e1 * wfe.z + bfv.z) * sp_f(pis.z + q1.z + e1 * wse.z + bsv.z);
            acc.w += sigm_f(pif.w + f1.w + e1 * wfe.w + bfv.w) * sp_f(pis.w + q1.w + e1 * wse.w + bsv.w);
        }
        if (k < end) {
            int s0 = g_esrc[k];
            float e0 = g_ee[k];
            const float4* Pj0 = (const float4*)(g_P + (size_t)s0 * 512 + 256);
            float4 f0 = Pj0[lane];
            float4 q0 = Pj0[32 + lane];
            acc.x += sigm_f(pif.x + f0.x + e0 * wfe.x + bfv.x) * sp_f(pis.x + q0.x + e0 * wse.x + bsv.x);
            acc.y += sigm_f(pif.y + f0.y + e0 * wfe.y + bfv.y) * sp_f(pis.y + q0.y + e0 * wse.y + bsv.y);
            acc.z += sigm_f(pif.z + f0.z + e0 * wfe.z + bfv.z) * sp_f(pis.z + q0.z + e0 * wse.z + bsv.z);
            acc.w += sigm_f(pif.w + f0.w + e0 * wfe.w + bfv.w) * sp_f(pis.w + q0.w + e0 * wse.w + bsv.w);
        }
        *(float4*)(g_aggr + (size_t)i * CC + c) = acc;
        lsum[0] += acc.x; lsum[1] += acc.y; lsum[2] += acc.z; lsum[3] += acc.w;
        lsq[0] += acc.x * acc.x; lsq[1] += acc.y * acc.y; lsq[2] += acc.z * acc.z; lsq[3] += acc.w * acc.w;
    }

#pragma unroll
    for (int j = 0; j < 4; j++) {
        atomicAdd(&s_stats[c + j], lsum[j]);
        atomicAdd(&s_stats[CC + c + j], lsq[j]);
    }
    __syncthreads();
    if (tid < 64) {
        float4 v = *(float4*)&s_stats[tid * 4];
        float* dstp = g_stats + tid * 4;
        asm volatile("red.global.add.v4.f32 [%0], {%1, %2, %3, %4};"
                     :: "l"(dstp), "f"(v.x), "f"(v.y), "f"(v.z), "f"(v.w)
                     : "memory");
    }
}

// ---------------- out_final = 2*out + batchnorm(aggr) ----------------
__global__ void finalize(const float* __restrict__ gamma, const float* __restrict__ beta,
                         float* __restrict__ out) {
    int i4 = blockIdx.x * blockDim.x + threadIdx.x;
    if (i4 >= NN * 32) return;
    int c = (i4 & 31) * 4;
    float4 a = *(const float4*)(g_aggr + (size_t)i4 * 4);
    float4 o = *(const float4*)(g_out + (size_t)i4 * 4);
    const float inv = 1.0f / NN;
    float4 r;
#pragma unroll
    for (int j = 0; j < 4; j++) {
        float sum = g_stats[c + j];
        float sq = g_stats[CC + c + j];
        float mean = sum * inv;
        float var = sq * inv - mean * mean;
        float scale = rsqrtf(var + 1e-5f) * gamma[c + j];
        float av = (&a.x)[j];
        float ov = (&o.x)[j];
        (&r.x)[j] = 2.0f * ov + (av - mean) * scale + beta[c + j];
    }
    *(float4*)(out + (size_t)i4 * 4) = r;
}

extern "C" void kernel_launch(void* const* d_in, const int* in_sizes, int n_in,
                              void* d_out, int out_size) {
    const float* h    = (const float*)d_in[0];
    const int*   ei   = (const int*)d_in[1];
    // d_in[2] = edge_weight (unused by reference)
    const float* ea   = (const float*)d_in[3];
    const float* W0   = (const float*)d_in[4];
    const float* b0   = (const float*)d_in[5];
    const float* Wsh  = (const float*)d_in[6];
    const float* bsh  = (const float*)d_in[7];
    const float* Wf   = (const float*)d_in[8];
    const float* bf   = (const float*)d_in[9];
    const float* Ws   = (const float*)d_in[10];
    const float* bs   = (const float*)d_in[11];
    const float* gamma = (const float*)d_in[12];
    const float* beta  = (const float*)d_in[13];
    float* out = (float*)d_out;

    float *p_out, *p_P, *p_Wcat, *p_stats;
    int *p_deg;
    cudaGetSymbolAddress((void**)&p_out, g_out);
    cudaGetSymbolAddress((void**)&p_P, g_P);
    cudaGetSymbolAddress((void**)&p_Wcat, g_Wcat);
    cudaGetSymbolAddress((void**)&p_stats, g_stats);
    cudaGetSymbolAddress((void**)&p_deg, g_deg);

    // Lazily-created side stream + fork/join events (host resources only).
    static cudaStream_t s2 = nullptr;
    static cudaEvent_t evFork = nullptr, evJoin = nullptr;
    if (!s2) {
        cudaStreamCreateWithFlags(&s2, cudaStreamNonBlocking);
        cudaEventCreateWithFlags(&evFork, cudaEventDisableTiming);
        cudaEventCreateWithFlags(&evJoin, cudaEventDisableTiming);
    }

    // ---- fork: edge/CSR pipeline on s2, node/GEMM pipeline on default ----
    cudaEventRecord(evFork, 0);
    cudaStreamWaitEvent(s2, evFork, 0);

    // stream s2: CSR build + edge gaussian (memory-bound)
    cudaMemsetAsync(p_deg, 0, NN * sizeof(int), s2);
    hist<<<(EE + 255) / 256, 256, 0, s2>>>(ei);
    scan_local<<<SCAN_BLOCKS, 256, 0, s2>>>();
    scan_bsums<<<1, 256, 0, s2>>>();
    scan_add<<<SCAN_BLOCKS, 256, 0, s2>>>();
    edge_gauss_scatter<<<(EE * 16 + 255) / 256, 256, 0, s2>>>(ea, Wsh, bsh, ei);
    cudaEventRecord(evJoin, s2);

    // default stream: weights + GEMMs (fma-bound)
    cudaMemsetAsync(p_stats, 0, 2 * CC * sizeof(float));
    prep_wcat<<<(KK * 512 + 255) / 256, 256>>>(Wf, Ws);
    gemm128<1><<<dim3((NN + 127) / 128, CC / 128), 256>>>(h, W0, b0, p_out, NN, CC);
    gemm128<0><<<dim3((NN + 127) / 128, 512 / 128), 256>>>(p_out, p_Wcat, nullptr, p_P, NN, 512);

    // ---- join ----
    cudaStreamWaitEvent(0, evJoin, 0);

    const int blocks = 1024;
    edge_msg_csr<<<blocks, 256>>>(Wf, Ws, bf, bs, blocks * 8);
    finalize<<<(NN * 32 + 255) / 256, 256>>>(gamma, beta, out);
}

// round 5
// speedup vs baseline: 1.3394x; 1.3394x over previous
#include <cuda_runtime.h>
#include <cuda_fp16.h>
#include <math.h>

#define NN 50000
#define EE 600000
#define CC 128
#define KK 128
#define SCAN_BLOCKS ((NN + 255) / 256)   // 196

// Scratch (static device globals; no runtime allocation allowed)
__device__ float  g_out[(size_t)NN * CC];      // softplus(h@W0+b0)
__device__ float  g_Pi[(size_t)NN * 256];      // fp32 [pi_f | pi_s] per node
__device__ __half g_Pj16[(size_t)NN * 256];    // fp16 [pj_f | pj_s] per node (gathered side)
__device__ float  g_aggr[(size_t)NN * CC];     // segment-sum result
__device__ float  g_stats[2 * CC];             // per-channel sum, sumsq
__device__ float  g_Wcat[KK * 512];            // packed [Wf_i|Ws_i|Wf_j|Ws_j]
// CSR scratch
__device__ int    g_deg[NN];
__device__ int    g_roff[NN];
__device__ int    g_cursor[NN];
__device__ int    g_bsum[SCAN_BLOCKS];
__device__ int    g_boff[SCAN_BLOCKS];
__device__ int    g_esrc[EE];                  // src sorted by dst
__device__ float  g_ee[EE];                    // e value sorted by dst

__device__ __forceinline__ float sp_f(float x) {
    return x > 15.0f ? x : __logf(1.0f + __expf(x));
}
__device__ __forceinline__ float sigm_f(float x) {
    return __fdividef(1.0f, 1.0f + __expf(-x));
}

// ---------------- weight packing ----------------
__global__ void prep_wcat(const float* __restrict__ Wf, const float* __restrict__ Ws) {
    int idx = blockIdx.x * blockDim.x + threadIdx.x;
    if (idx >= KK * 512) return;
    int k = idx >> 9;
    int c = idx & 511;
    float v;
    if (c < 128)      v = Wf[k * 128 + c];
    else if (c < 256) v = Ws[k * 128 + (c - 128)];
    else if (c < 384) v = Wf[(128 + k) * 128 + (c - 256)];
    else              v = Ws[(128 + k) * 128 + (c - 384)];
    g_Wcat[idx] = v;
}

// ---------------- GEMM (fp32, 128x128 tile, 8x8 microtile) ----------------
// MODE 0: plain fp32 out (Co). MODE 1: softplus+bias fp32 out (Co).
// MODE 2: split epilogue for P: cols [0,256) -> g_Pi fp32; cols [256,512) -> g_Pj16 fp16.
template <int MODE>
__global__ void __launch_bounds__(256, 2)
gemm128(const float* __restrict__ A, const float* __restrict__ B,
        const float* __restrict__ bias, float* __restrict__ Co,
        int M, int Nc) {
    __shared__ float As[16][132];
    __shared__ float Bs[16][128];
    int tid = threadIdx.x;
    int tx = tid & 15, ty = tid >> 4;
    int row0 = blockIdx.x * 128, col0 = blockIdx.y * 128;
    float acc[8][8] = {};

    for (int kc = 0; kc < KK; kc += 16) {
#pragma unroll
        for (int l = 0; l < 2; l++) {
            int f = tid + l * 256;
            int m = f >> 2;
            int kq = (f & 3) << 2;
            int gr = row0 + m;
            float4 av = make_float4(0.f, 0.f, 0.f, 0.f);
            if (gr < M) av = *(const float4*)(A + (size_t)gr * KK + kc + kq);
            As[kq + 0][m] = av.x;
            As[kq + 1][m] = av.y;
            As[kq + 2][m] = av.z;
            As[kq + 3][m] = av.w;
        }
#pragma unroll
        for (int l = 0; l < 2; l++) {
            int f = tid + l * 256;
            int k = f >> 5;
            int c4 = (f & 31) << 2;
            *(float4*)&Bs[k][c4] = *(const float4*)(B + (size_t)(kc + k) * Nc + col0 + c4);
        }
        __syncthreads();

#pragma unroll
        for (int k = 0; k < 16; k++) {
            float4 a0 = *(float4*)&As[k][ty * 4];
            float4 a1 = *(float4*)&As[k][64 + ty * 4];
            float4 b0 = *(float4*)&Bs[k][tx * 4];
            float4 b1 = *(float4*)&Bs[k][64 + tx * 4];
            float ar[8] = {a0.x, a0.y, a0.z, a0.w, a1.x, a1.y, a1.z, a1.w};
            float br[8] = {b0.x, b0.y, b0.z, b0.w, b1.x, b1.y, b1.z, b1.w};
#pragma unroll
            for (int i = 0; i < 8; i++)
#pragma unroll
                for (int j = 0; j < 8; j++)
                    acc[i][j] += ar[i] * br[j];
        }
        __syncthreads();
    }

#pragma unroll
    for (int i = 0; i < 8; i++) {
        int gr = row0 + (i < 4 ? ty * 4 + i : 64 + ty * 4 + (i - 4));
        if (gr >= M) continue;
#pragma unroll
        for (int half = 0; half < 2; half++) {
            int gc = col0 + half * 64 + tx * 4;
            float4 v;
            v.x = acc[i][half * 4 + 0];
            v.y = acc[i][half * 4 + 1];
            v.z = acc[i][half * 4 + 2];
            v.w = acc[i][half * 4 + 3];
            if (MODE == 1) {
                v.x = sp_f(v.x + bias[gc + 0]);
                v.y = sp_f(v.y + bias[gc + 1]);
                v.z = sp_f(v.z + bias[gc + 2]);
                v.w = sp_f(v.w + bias[gc + 3]);
            }
            if (MODE == 2) {
                if (gc < 256) {
                    *(float4*)(g_Pi + (size_t)gr * 256 + gc) = v;
                } else {
                    __half2 h0 = __floats2half2_rn(v.x, v.y);
                    __half2 h1 = __floats2half2_rn(v.z, v.w);
                    uint2 u;
                    u.x = *(unsigned*)&h0;
                    u.y = *(unsigned*)&h1;
                    *(uint2*)(g_Pj16 + (size_t)gr * 256 + (gc - 256)) = u;
                }
            } else {
                *(float4*)(Co + (size_t)gr * Nc + gc) = v;
            }
        }
    }
}

// ---------------- CSR build ----------------
__global__ void hist(const int* __restrict__ ei) {
    int e = blockIdx.x * blockDim.x + threadIdx.x;
    if (e < EE) atomicAdd(&g_deg[ei[EE + e]], 1);
}

__global__ void scan_local() {
    __shared__ int s[256];
    int tid = threadIdx.x;
    int i = blockIdx.x * 256 + tid;
    int v = (i < NN) ? g_deg[i] : 0;
    s[tid] = v;
    __syncthreads();
#pragma unroll
    for (int off = 1; off < 256; off <<= 1) {
        int t = (tid >= off) ? s[tid - off] : 0;
        __syncthreads();
        s[tid] += t;
        __syncthreads();
    }
    if (i < NN) g_roff[i] = s[tid] - v;     // exclusive
    if (tid == 255) g_bsum[blockIdx.x] = s[255];
}

__global__ void scan_bsums() {
    __shared__ int s[256];
    int tid = threadIdx.x;
    int v = (tid < SCAN_BLOCKS) ? g_bsum[tid] : 0;
    s[tid] = v;
    __syncthreads();
#pragma unroll
    for (int off = 1; off < 256; off <<= 1) {
        int t = (tid >= off) ? s[tid - off] : 0;
        __syncthreads();
        s[tid] += t;
        __syncthreads();
    }
    if (tid < SCAN_BLOCKS) g_boff[tid] = s[tid] - v;   // exclusive
}

__global__ void scan_add() {
    int i = blockIdx.x * 256 + threadIdx.x;
    if (i < NN) {
        int r = g_roff[i] + g_boff[blockIdx.x];
        g_roff[i] = r;
        g_cursor[i] = r;
    }
}

// ---------------- e = softplus(edge_attr @ Wsh + bsh) fused with CSR scatter
__global__ void edge_gauss_scatter(const float* __restrict__ ea,
                                   const float* __restrict__ Wsh,
                                   const float* __restrict__ bsh,
                                   const int* __restrict__ ei) {
    int t = blockIdx.x * blockDim.x + threadIdx.x;
    int e = t >> 4;
    if (e >= EE) return;
    int l = t & 15;
    const float* base = ea + (size_t)e * 128;
    float4 a0 = *(const float4*)(base + l * 4);
    float4 a1 = *(const float4*)(base + 64 + l * 4);
    float4 w0 = *(const float4*)(Wsh + l * 4);
    float4 w1 = *(const float4*)(Wsh + 64 + l * 4);
    float d = a0.x * w0.x + a0.y * w0.y + a0.z * w0.z + a0.w * w0.w
            + a1.x * w1.x + a1.y * w1.y + a1.z * w1.z + a1.w * w1.w;
#pragma unroll
    for (int o = 8; o; o >>= 1) d += __shfl_xor_sync(0xFFFFFFFFu, d, o);
    if (l == 0) {
        float ev = sp_f(d + bsh[0]);
        int src = __ldg(ei + e);
        int dst = __ldg(ei + EE + e);
        int pos = atomicAdd(&g_cursor[dst], 1);
        g_esrc[pos] = src;
        g_ee[pos] = ev;
    }
}

// ---------------- CSR edge messages + fused BN stats ----------------
// One warp per dst node (strided). pi (fp32) loaded once per node; pj gathered
// as fp16 (512B/edge, L2-resident); inner loop unrolled x2 for MLP;
// plain stores to g_aggr; block stats -> red.global.
__device__ __forceinline__ void pj_load(int src, int lane, float4& f, float4& q) {
    const __half* base = g_Pj16 + (size_t)src * 256;
    uint2 uf = *(const uint2*)(base + lane * 4);
    uint2 uq = *(const uint2*)(base + 128 + lane * 4);
    float2 f01 = __half22float2(*(__half2*)&uf.x);
    float2 f23 = __half22float2(*(__half2*)&uf.y);
    float2 q01 = __half22float2(*(__half2*)&uq.x);
    float2 q23 = __half22float2(*(__half2*)&uq.y);
    f = make_float4(f01.x, f01.y, f23.x, f23.y);
    q = make_float4(q01.x, q01.y, q23.x, q23.y);
}

__global__ void __launch_bounds__(256)
edge_msg_csr(const float* __restrict__ Wf, const float* __restrict__ Ws,
             const float* __restrict__ bf, const float* __restrict__ bs,
             int nwarps) {
    __shared__ float s_stats[2 * CC];
    int tid = threadIdx.x;
    int lane = tid & 31;
    int c = lane * 4;
    s_stats[tid] = 0.0f;
    __syncthreads();

    float4 wfe = *(const float4*)(Wf + 256 * 128 + c);
    float4 wse = *(const float4*)(Ws + 256 * 128 + c);
    float4 bfv = *(const float4*)(bf + c);
    float4 bsv = *(const float4*)(bs + c);

    float lsum[4] = {}, lsq[4] = {};

    int gw = blockIdx.x * 8 + (tid >> 5);
    for (int i = gw; i < NN; i += nwarps) {
        const float4* Pi = (const float4*)(g_Pi + (size_t)i * 256);
        float4 pif = Pi[lane];
        float4 pis = Pi[32 + lane];
        // fold biases in once per node
        pif.x += bfv.x; pif.y += bfv.y; pif.z += bfv.z; pif.w += bfv.w;
        pis.x += bsv.x; pis.y += bsv.y; pis.z += bsv.z; pis.w += bsv.w;
        int k = g_roff[i];
        int end = g_cursor[i];
        float4 acc = make_float4(0.f, 0.f, 0.f, 0.f);

        for (; k + 2 <= end; k += 2) {
            int s0 = g_esrc[k], s1 = g_esrc[k + 1];
            float e0 = g_ee[k], e1 = g_ee[k + 1];
            float4 f0, q0, f1, q1;
            pj_load(s0, lane, f0, q0);
            pj_load(s1, lane, f1, q1);
            acc.x += sigm_f(pif.x + f0.x + e0 * wfe.x) * sp_f(pis.x + q0.x + e0 * wse.x);
            acc.y += sigm_f(pif.y + f0.y + e0 * wfe.y) * sp_f(pis.y + q0.y + e0 * wse.y);
            acc.z += sigm_f(pif.z + f0.z + e0 * wfe.z) * sp_f(pis.z + q0.z + e0 * wse.z);
            acc.w += sigm_f(pif.w + f0.w + e0 * wfe.w) * sp_f(pis.w + q0.w + e0 * wse.w);
            acc.x += sigm_f(pif.x + f1.x + e1 * wfe.x) * sp_f(pis.x + q1.x + e1 * wse.x);
            acc.y += sigm_f(pif.y + f1.y + e1 * wfe.y) * sp_f(pis.y + q1.y + e1 * wse.y);
            acc.z += sigm_f(pif.z + f1.z + e1 * wfe.z) * sp_f(pis.z + q1.z + e1 * wse.z);
            acc.w += sigm_f(pif.w + f1.w + e1 * wfe.w) * sp_f(pis.w + q1.w + e1 * wse.w);
        }
        if (k < end) {
            int s0 = g_esrc[k];
            float e0 = g_ee[k];
            float4 f0, q0;
            pj_load(s0, lane, f0, q0);
            acc.x += sigm_f(pif.x + f0.x + e0 * wfe.x) * sp_f(pis.x + q0.x + e0 * wse.x);
            acc.y += sigm_f(pif.y + f0.y + e0 * wfe.y) * sp_f(pis.y + q0.y + e0 * wse.y);
            acc.z += sigm_f(pif.z + f0.z + e0 * wfe.z) * sp_f(pis.z + q0.z + e0 * wse.z);
            acc.w += sigm_f(pif.w + f0.w + e0 * wfe.w) * sp_f(pis.w + q0.w + e0 * wse.w);
        }
        *(float4*)(g_aggr + (size_t)i * CC + c) = acc;
        lsum[0] += acc.x; lsum[1] += acc.y; lsum[2] += acc.z; lsum[3] += acc.w;
        lsq[0] += acc.x * acc.x; lsq[1] += acc.y * acc.y; lsq[2] += acc.z * acc.z; lsq[3] += acc.w * acc.w;
    }

#pragma unroll
    for (int j = 0; j < 4; j++) {
        atomicAdd(&s_stats[c + j], lsum[j]);
        atomicAdd(&s_stats[CC + c + j], lsq[j]);
    }
    __syncthreads();
    if (tid < 64) {
        float4 v = *(float4*)&s_stats[tid * 4];
        float* dstp = g_stats + tid * 4;
        asm volatile("red.global.add.v4.f32 [%0], {%1, %2, %3, %4};"
                     :: "l"(dstp), "f"(v.x), "f"(v.y), "f"(v.z), "f"(v.w)
                     : "memory");
    }
}

// ---------------- out_final = 2*out + batchnorm(aggr) ----------------
__global__ void finalize(const float* __restrict__ gamma, const float* __restrict__ beta,
                         float* __restrict__ out) {
    int i4 = blockIdx.x * blockDim.x + threadIdx.x;
    if (i4 >= NN * 32) return;
    int c = (i4 & 31) * 4;
    float4 a = *(const float4*)(g_aggr + (size_t)i4 * 4);
    float4 o = *(const float4*)(g_out + (size_t)i4 * 4);
    const float inv = 1.0f / NN;
    float4 r;
#pragma unroll
    for (int j = 0; j < 4; j++) {
        float sum = g_stats[c + j];
        float sq = g_stats[CC + c + j];
        float mean = sum * inv;
        float var = sq * inv - mean * mean;
        float scale = rsqrtf(var + 1e-5f) * gamma[c + j];
        float av = (&a.x)[j];
        float ov = (&o.x)[j];
        (&r.x)[j] = 2.0f * ov + (av - mean) * scale + beta[c + j];
    }
    *(float4*)(out + (size_t)i4 * 4) = r;
}

extern "C" void kernel_launch(void* const* d_in, const int* in_sizes, int n_in,
                              void* d_out, int out_size) {
    const float* h    = (const float*)d_in[0];
    const int*   ei   = (const int*)d_in[1];
    // d_in[2] = edge_weight (unused by reference)
    const float* ea   = (const float*)d_in[3];
    const float* W0   = (const float*)d_in[4];
    const float* b0   = (const float*)d_in[5];
    const float* Wsh  = (const float*)d_in[6];
    const float* bsh  = (const float*)d_in[7];
    const float* Wf   = (const float*)d_in[8];
    const float* bf   = (const float*)d_in[9];
    const float* Ws   = (const float*)d_in[10];
    const float* bs   = (const float*)d_in[11];
    const float* gamma = (const float*)d_in[12];
    const float* beta  = (const float*)d_in[13];
    float* out = (float*)d_out;

    float *p_out, *p_Wcat, *p_stats;
    int *p_deg;
    cudaGetSymbolAddress((void**)&p_out, g_out);
    cudaGetSymbolAddress((void**)&p_Wcat, g_Wcat);
    cudaGetSymbolAddress((void**)&p_stats, g_stats);
    cudaGetSymbolAddress((void**)&p_deg, g_deg);

    static cudaStream_t s2 = nullptr;
    static cudaEvent_t evFork = nullptr, evJoin = nullptr;
    if (!s2) {
        cudaStreamCreateWithFlags(&s2, cudaStreamNonBlocking);
        cudaEventCreateWithFlags(&evFork, cudaEventDisableTiming);
        cudaEventCreateWithFlags(&evJoin, cudaEventDisableTiming);
    }

    // ---- fork: edge/CSR pipeline on s2, node/GEMM pipeline on default ----
    cudaEventRecord(evFork, 0);
    cudaStreamWaitEvent(s2, evFork, 0);

    cudaMemsetAsync(p_deg, 0, NN * sizeof(int), s2);
    hist<<<(EE + 255) / 256, 256, 0, s2>>>(ei);
    scan_local<<<SCAN_BLOCKS, 256, 0, s2>>>();
    scan_bsums<<<1, 256, 0, s2>>>();
    scan_add<<<SCAN_BLOCKS, 256, 0, s2>>>();
    edge_gauss_scatter<<<(EE * 16 + 255) / 256, 256, 0, s2>>>(ea, Wsh, bsh, ei);
    cudaEventRecord(evJoin, s2);

    cudaMemsetAsync(p_stats, 0, 2 * CC * sizeof(float));
    prep_wcat<<<(KK * 512 + 255) / 256, 256>>>(Wf, Ws);
    gemm128<1><<<dim3((NN + 127) / 128, CC / 128), 256>>>(h, W0, b0, p_out, NN, CC);
    gemm128<2><<<dim3((NN + 127) / 128, 512 / 128), 256>>>(p_out, p_Wcat, nullptr, nullptr, NN, 512);

    cudaStreamWaitEvent(0, evJoin, 0);

    const int blocks = 1024;
    edge_msg_csr<<<blocks, 256>>>(Wf, Ws, bf, bs, blocks * 8);
    finalize<<<(NN * 32 + 255) / 256, 256>>>(gamma, beta, out);
}

// round 6
// speedup vs baseline: 1.7143x; 1.2799x over previous
#include <cuda_runtime.h>
#include <cuda_fp16.h>
#include <math.h>

#define NN 50000
#define EE 600000
#define CC 128
#define KK 128
#define SCAN_BLOCKS ((NN + 255) / 256)   // 196
#define LDH 136                           // padded smem row, halves (136*2B, /16B ok)

// Scratch (static device globals; no runtime allocation allowed)
__device__ float  g_out[(size_t)NN * CC];      // softplus(h@W0+b0) fp32
__device__ __half g_out16[(size_t)NN * CC];    // fp16 copy (A of TC GEMM)
__device__ float  g_Pi[(size_t)NN * 256];      // fp32 [pi_f | pi_s] per node
__device__ __half g_Pj16[(size_t)NN * 256];    // fp16 [pj_f | pj_s] per node
__device__ float  g_aggr[(size_t)NN * CC];     // segment-sum result
__device__ float  g_stats[2 * CC];             // per-channel sum, sumsq
__device__ __half g_Wcat16T[512 * 128];        // packed weights, TRANSPOSED [n][k], fp16
// CSR scratch
__device__ int    g_deg[NN];
__device__ int    g_roff[NN];
__device__ int    g_cursor[NN];
__device__ int    g_bsum[SCAN_BLOCKS];
__device__ int    g_boff[SCAN_BLOCKS];
__device__ int2   g_epack[EE];                 // (src, e-bits) sorted by dst

__device__ __forceinline__ float sp_f(float x) {
    return x > 15.0f ? x : __logf(1.0f + __expf(x));
}
__device__ __forceinline__ float sigm_f(float x) {
    return __fdividef(1.0f, 1.0f + __expf(-x));
}

// ---------------- weight packing (fp16, transposed [n][k]) ----------------
// n: 0-127 = Wf[:128] (x_i), 128-255 = Ws[:128], 256-383 = Wf[128:], 384-511 = Ws[128:]
__global__ void prep_wcat(const float* __restrict__ Wf, const float* __restrict__ Ws) {
    int idx = blockIdx.x * blockDim.x + threadIdx.x;   // n*128 + k
    if (idx >= 512 * 128) return;
    int n = idx >> 7;
    int k = idx & 127;
    float v;
    if (n < 128)      v = Wf[k * 128 + n];
    else if (n < 256) v = Ws[k * 128 + (n - 128)];
    else if (n < 384) v = Wf[(128 + k) * 128 + (n - 256)];
    else              v = Ws[(128 + k) * 128 + (n - 384)];
    g_Wcat16T[idx] = __float2half(v);
}

// ---------------- GEMM1 (fp32 SIMT): out = softplus(h@W0 + b0), + fp16 copy ----
__global__ void __launch_bounds__(256, 2)
gemm1(const float* __restrict__ A, const float* __restrict__ B,
      const float* __restrict__ bias, int M) {
    __shared__ float As[16][132];
    __shared__ float Bs[16][128];
    int tid = threadIdx.x;
    int tx = tid & 15, ty = tid >> 4;
    int row0 = blockIdx.x * 128;
    float acc[8][8] = {};

    for (int kc = 0; kc < KK; kc += 16) {
#pragma unroll
        for (int l = 0; l < 2; l++) {
            int f = tid + l * 256;
            int m = f >> 2;
            int kq = (f & 3) << 2;
            int gr = row0 + m;
            float4 av = make_float4(0.f, 0.f, 0.f, 0.f);
            if (gr < M) av = *(const float4*)(A + (size_t)gr * KK + kc + kq);
            As[kq + 0][m] = av.x;
            As[kq + 1][m] = av.y;
            As[kq + 2][m] = av.z;
            As[kq + 3][m] = av.w;
        }
#pragma unroll
        for (int l = 0; l < 2; l++) {
            int f = tid + l * 256;
            int k = f >> 5;
            int c4 = (f & 31) << 2;
            *(float4*)&Bs[k][c4] = *(const float4*)(B + (size_t)(kc + k) * CC + c4);
        }
        __syncthreads();
#pragma unroll
        for (int k = 0; k < 16; k++) {
            float4 a0 = *(float4*)&As[k][ty * 4];
            float4 a1 = *(float4*)&As[k][64 + ty * 4];
            float4 b0 = *(float4*)&Bs[k][tx * 4];
            float4 b1 = *(float4*)&Bs[k][64 + tx * 4];
            float ar[8] = {a0.x, a0.y, a0.z, a0.w, a1.x, a1.y, a1.z, a1.w};
            float br[8] = {b0.x, b0.y, b0.z, b0.w, b1.x, b1.y, b1.z, b1.w};
#pragma unroll
            for (int i = 0; i < 8; i++)
#pragma unroll
                for (int j = 0; j < 8; j++)
                    acc[i][j] += ar[i] * br[j];
        }
        __syncthreads();
    }

#pragma unroll
    for (int i = 0; i < 8; i++) {
        int gr = row0 + (i < 4 ? ty * 4 + i : 64 + ty * 4 + (i - 4));
        if (gr >= M) continue;
#pragma unroll
        for (int half = 0; half < 2; half++) {
            int gc = half * 64 + tx * 4;
            float4 v;
            v.x = sp_f(acc[i][half * 4 + 0] + bias[gc + 0]);
            v.y = sp_f(acc[i][half * 4 + 1] + bias[gc + 1]);
            v.z = sp_f(acc[i][half * 4 + 2] + bias[gc + 2]);
            v.w = sp_f(acc[i][half * 4 + 3] + bias[gc + 3]);
            *(float4*)(g_out + (size_t)gr * CC + gc) = v;
            __half2 h0 = __floats2half2_rn(v.x, v.y);
            __half2 h1 = __floats2half2_rn(v.z, v.w);
            uint2 u;
            u.x = *(unsigned*)&h0;
            u.y = *(unsigned*)&h1;
            *(uint2*)(g_out16 + (size_t)gr * CC + gc) = u;
        }
    }
}

// ---------------- GEMM2 (fp16 tensor core): P = out @ Wcat ----------------
// 128x128 block tile, full K=128 resident in smem, 8 warps (2M x 4N),
// warp tile 64x32 = 4x4 m16n8k16 mma per k-step, 8 k-steps.
// Epilogue: blockIdx.y<2 -> g_Pi fp32; else -> g_Pj16 fp16.
__global__ void __launch_bounds__(256, 2)
gemm2_tc() {
    extern __shared__ __half smemh[];
    __half* As = smemh;                 // [128][LDH]
    __half* Bs = smemh + 128 * LDH;     // [128][LDH], row n, col k
    int tid = threadIdx.x;
    int row0 = blockIdx.x * 128;
    int nblk = blockIdx.y;

#pragma unroll
    for (int l = 0; l < 8; l++) {
        int idx = tid + l * 256;        // 0..2047
        int r = idx >> 4;
        int c8 = (idx & 15) << 3;
        int4 v = make_int4(0, 0, 0, 0);
        int gr = row0 + r;
        if (gr < NN) v = *(const int4*)(g_out16 + (size_t)gr * CC + c8);
        *(int4*)(As + r * LDH + c8) = v;
        int4 w = *(const int4*)(g_Wcat16T + ((size_t)(nblk * 128 + r)) * CC + c8);
        *(int4*)(Bs + r * LDH + c8) = w;
    }
    __syncthreads();

    int lane = tid & 31;
    int w = tid >> 5;
    int g = lane >> 2, tig = lane & 3;
    int wm = (w & 1) * 64, wn = (w >> 1) * 32;

    float acc[4][4][4];
#pragma unroll
    for (int mt = 0; mt < 4; mt++)
#pragma unroll
        for (int nt = 0; nt < 4; nt++)
#pragma unroll
            for (int q = 0; q < 4; q++) acc[mt][nt][q] = 0.f;

    const unsigned* As2 = (const unsigned*)As;   // half2 view, row stride 68
    const unsigned* Bs2 = (const unsigned*)Bs;

#pragma unroll
    for (int ks = 0; ks < 8; ks++) {
        int kk = ks * 8;                 // half2 offset
        unsigned a[4][4], b[4][2];
#pragma unroll
        for (int mt = 0; mt < 4; mt++) {
            int r = wm + mt * 16 + g;
            a[mt][0] = As2[r * 68 + kk + tig];
            a[mt][1] = As2[(r + 8) * 68 + kk + tig];
            a[mt][2] = As2[r * 68 + kk + 4 + tig];
            a[mt][3] = As2[(r + 8) * 68 + kk + 4 + tig];
        }
#pragma unroll
        for (int nt = 0; nt < 4; nt++) {
            int r = wn + nt * 8 + g;
            b[nt][0] = Bs2[r * 68 + kk + tig];
            b[nt][1] = Bs2[r * 68 + kk + 4 + tig];
        }
#pragma unroll
        for (int mt = 0; mt < 4; mt++)
#pragma unroll
            for (int nt = 0; nt < 4; nt++) {
                asm volatile(
                    "mma.sync.aligned.m16n8k16.row.col.f32.f16.f16.f32 "
                    "{%0,%1,%2,%3}, {%4,%5,%6,%7}, {%8,%9}, {%0,%1,%2,%3};"
                    : "+f"(acc[mt][nt][0]), "+f"(acc[mt][nt][1]),
                      "+f"(acc[mt][nt][2]), "+f"(acc[mt][nt][3])
                    : "r"(a[mt][0]), "r"(a[mt][1]), "r"(a[mt][2]), "r"(a[mt][3]),
                      "r"(b[nt][0]), "r"(b[nt][1]));
            }
    }

    // Epilogue
#pragma unroll
    for (int mt = 0; mt < 4; mt++) {
#pragma unroll
        for (int nt = 0; nt < 4; nt++) {
            int gr0 = row0 + wm + mt * 16 + g;
            int gr1 = gr0 + 8;
            int col = nblk * 128 + wn + nt * 8 + tig * 2;   // 0..511
            float d0 = acc[mt][nt][0], d1 = acc[mt][nt][1];
            float d2 = acc[mt][nt][2], d3 = acc[mt][nt][3];
            if (nblk < 2) {
                if (gr0 < NN) *(float2*)(g_Pi + (size_t)gr0 * 256 + col) = make_float2(d0, d1);
                if (gr1 < NN) *(float2*)(g_Pi + (size_t)gr1 * 256 + col) = make_float2(d2, d3);
            } else {
                int cj = col - 256;
                __half2 h01 = __floats2half2_rn(d0, d1);
                __half2 h23 = __floats2half2_rn(d2, d3);
                if (gr0 < NN) *(unsigned*)(g_Pj16 + (size_t)gr0 * 256 + cj) = *(unsigned*)&h01;
                if (gr1 < NN) *(unsigned*)(g_Pj16 + (size_t)gr1 * 256 + cj) = *(unsigned*)&h23;
            }
        }
    }
}

// ---------------- CSR build ----------------
__global__ void hist(const int* __restrict__ ei) {
    int e = blockIdx.x * blockDim.x + threadIdx.x;
    if (e < EE) atomicAdd(&g_deg[ei[EE + e]], 1);
}

__global__ void scan_local() {
    __shared__ int s[256];
    int tid = threadIdx.x;
    int i = blockIdx.x * 256 + tid;
    int v = (i < NN) ? g_deg[i] : 0;
    s[tid] = v;
    __syncthreads();
#pragma unroll
    for (int off = 1; off < 256; off <<= 1) {
        int t = (tid >= off) ? s[tid - off] : 0;
        __syncthreads();
        s[tid] += t;
        __syncthreads();
    }
    if (i < NN) g_roff[i] = s[tid] - v;
    if (tid == 255) g_bsum[blockIdx.x] = s[255];
}

__global__ void scan_bsums() {
    __shared__ int s[256];
    int tid = threadIdx.x;
    int v = (tid < SCAN_BLOCKS) ? g_bsum[tid] : 0;
    s[tid] = v;
    __syncthreads();
#pragma unroll
    for (int off = 1; off < 256; off <<= 1) {
        int t = (tid >= off) ? s[tid - off] : 0;
        __syncthreads();
        s[tid] += t;
        __syncthreads();
    }
    if (tid < SCAN_BLOCKS) g_boff[tid] = s[tid] - v;
}

__global__ void scan_add() {
    int i = blockIdx.x * 256 + threadIdx.x;
    if (i < NN) {
        int r = g_roff[i] + g_boff[blockIdx.x];
        g_roff[i] = r;
        g_cursor[i] = r;
    }
}

// ---------------- e = softplus(edge_attr @ Wsh + bsh) fused with CSR scatter
__global__ void edge_gauss_scatter(const float* __restrict__ ea,
                                   const float* __restrict__ Wsh,
                                   const float* __restrict__ bsh,
                                   const int* __restrict__ ei) {
    int t = blockIdx.x * blockDim.x + threadIdx.x;
    int e = t >> 4;
    if (e >= EE) return;
    int l = t & 15;
    const float* base = ea + (size_t)e * 128;
    float4 a0 = *(const float4*)(base + l * 4);
    float4 a1 = *(const float4*)(base + 64 + l * 4);
    float4 w0 = *(const float4*)(Wsh + l * 4);
    float4 w1 = *(const float4*)(Wsh + 64 + l * 4);
    float d = a0.x * w0.x + a0.y * w0.y + a0.z * w0.z + a0.w * w0.w
            + a1.x * w1.x + a1.y * w1.y + a1.z * w1.z + a1.w * w1.w;
#pragma unroll
    for (int o = 8; o; o >>= 1) d += __shfl_xor_sync(0xFFFFFFFFu, d, o);
    if (l == 0) {
        float ev = sp_f(d + bsh[0]);
        int src = __ldg(ei + e);
        int dst = __ldg(ei + EE + e);
        int pos = atomicAdd(&g_cursor[dst], 1);
        g_epack[pos] = make_int2(src, __float_as_int(ev));
    }
}

// ---------------- CSR edge messages + fused BN stats ----------------
__device__ __forceinline__ void pj_load(int src, int lane, float4& f, float4& q) {
    const __half* base = g_Pj16 + (size_t)src * 256;
    uint2 uf = *(const uint2*)(base + lane * 4);
    uint2 uq = *(const uint2*)(base + 128 + lane * 4);
    float2 f01 = __half22float2(*(__half2*)&uf.x);
    float2 f23 = __half22float2(*(__half2*)&uf.y);
    float2 q01 = __half22float2(*(__half2*)&uq.x);
    float2 q23 = __half22float2(*(__half2*)&uq.y);
    f = make_float4(f01.x, f01.y, f23.x, f23.y);
    q = make_float4(q01.x, q01.y, q23.x, q23.y);
}

__device__ __forceinline__ void msg_add(float4& acc, const float4& pif, const float4& pis,
                                        const float4& f, const float4& q, float ev,
                                        const float4& wfe, const float4& wse) {
    acc.x += sigm_f(pif.x + f.x + ev * wfe.x) * sp_f(pis.x + q.x + ev * wse.x);
    acc.y += sigm_f(pif.y + f.y + ev * wfe.y) * sp_f(pis.y + q.y + ev * wse.y);
    acc.z += sigm_f(pif.z + f.z + ev * wfe.z) * sp_f(pis.z + q.z + ev * wse.z);
    acc.w += sigm_f(pif.w + f.w + ev * wfe.w) * sp_f(pis.w + q.w + ev * wse.w);
}

__global__ void __launch_bounds__(256)
edge_msg_csr(const float* __restrict__ Wf, const float* __restrict__ Ws,
             const float* __restrict__ bf, const float* __restrict__ bs,
             int nwarps) {
    __shared__ float s_stats[2 * CC];
    int tid = threadIdx.x;
    int lane = tid & 31;
    int c = lane * 4;
    s_stats[tid] = 0.0f;
    __syncthreads();

    float4 wfe = *(const float4*)(Wf + 256 * 128 + c);
    float4 wse = *(const float4*)(Ws + 256 * 128 + c);
    float4 bfv = *(const float4*)(bf + c);
    float4 bsv = *(const float4*)(bs + c);

    float lsum[4] = {}, lsq[4] = {};

    int gw = blockIdx.x * 8 + (tid >> 5);
    for (int i = gw; i < NN; i += nwarps) {
        const float4* Pi = (const float4*)(g_Pi + (size_t)i * 256);
        float4 pif = Pi[lane];
        float4 pis = Pi[32 + lane];
        pif.x += bfv.x; pif.y += bfv.y; pif.z += bfv.z; pif.w += bfv.w;
        pis.x += bsv.x; pis.y += bsv.y; pis.z += bsv.z; pis.w += bsv.w;
        int k = g_roff[i];
        int end = g_cursor[i];
        float4 acc = make_float4(0.f, 0.f, 0.f, 0.f);

        for (; k + 4 <= end; k += 4) {
            int2 p0 = g_epack[k], p1 = g_epack[k + 1], p2 = g_epack[k + 2], p3 = g_epack[k + 3];
            float4 f0, q0, f1, q1, f2, q2, f3, q3;
            pj_load(p0.x, lane, f0, q0);
            pj_load(p1.x, lane, f1, q1);
            pj_load(p2.x, lane, f2, q2);
            pj_load(p3.x, lane, f3, q3);
            msg_add(acc, pif, pis, f0, q0, __int_as_float(p0.y), wfe, wse);
            msg_add(acc, pif, pis, f1, q1, __int_as_float(p1.y), wfe, wse);
            msg_add(acc, pif, pis, f2, q2, __int_as_float(p2.y), wfe, wse);
            msg_add(acc, pif, pis, f3, q3, __int_as_float(p3.y), wfe, wse);
        }
        for (; k < end; k++) {
            int2 p0 = g_epack[k];
            float4 f0, q0;
            pj_load(p0.x, lane, f0, q0);
            msg_add(acc, pif, pis, f0, q0, __int_as_float(p0.y), wfe, wse);
        }
        *(float4*)(g_aggr + (size_t)i * CC + c) = acc;
        lsum[0] += acc.x; lsum[1] += acc.y; lsum[2] += acc.z; lsum[3] += acc.w;
        lsq[0] += acc.x * acc.x; lsq[1] += acc.y * acc.y; lsq[2] += acc.z * acc.z; lsq[3] += acc.w * acc.w;
    }

#pragma unroll
    for (int j = 0; j < 4; j++) {
        atomicAdd(&s_stats[c + j], lsum[j]);
        atomicAdd(&s_stats[CC + c + j], lsq[j]);
    }
    __syncthreads();
    if (tid < 64) {
        float4 v = *(float4*)&s_stats[tid * 4];
        float* dstp = g_stats + tid * 4;
        asm volatile("red.global.add.v4.f32 [%0], {%1, %2, %3, %4};"
                     :: "l"(dstp), "f"(v.x), "f"(v.y), "f"(v.z), "f"(v.w)
                     : "memory");
    }
}

// ---------------- out_final = 2*out + batchnorm(aggr) ----------------
__global__ void finalize(const float* __restrict__ gamma, const float* __restrict__ beta,
                         float* __restrict__ out) {
    int i4 = blockIdx.x * blockDim.x + threadIdx.x;
    if (i4 >= NN * 32) return;
    int c = (i4 & 31) * 4;
    float4 a = *(const float4*)(g_aggr + (size_t)i4 * 4);
    float4 o = *(const float4*)(g_out + (size_t)i4 * 4);
    const float inv = 1.0f / NN;
    float4 r;
#pragma unroll
    for (int j = 0; j < 4; j++) {
        float sum = g_stats[c + j];
        float sq = g_stats[CC + c + j];
        float mean = sum * inv;
        float var = sq * inv - mean * mean;
        float scale = rsqrtf(var + 1e-5f) * gamma[c + j];
        float av = (&a.x)[j];
        float ov = (&o.x)[j];
        (&r.x)[j] = 2.0f * ov + (av - mean) * scale + beta[c + j];
    }
    *(float4*)(out + (size_t)i4 * 4) = r;
}

extern "C" void kernel_launch(void* const* d_in, const int* in_sizes, int n_in,
                              void* d_out, int out_size) {
    const float* h    = (const float*)d_in[0];
    const int*   ei   = (const int*)d_in[1];
    // d_in[2] = edge_weight (unused by reference)
    const float* ea   = (const float*)d_in[3];
    const float* W0   = (const float*)d_in[4];
    const float* b0   = (const float*)d_in[5];
    const float* Wsh  = (const float*)d_in[6];
    const float* bsh  = (const float*)d_in[7];
    const float* Wf   = (const float*)d_in[8];
    const float* bf   = (const float*)d_in[9];
    const float* Ws   = (const float*)d_in[10];
    const float* bs   = (const float*)d_in[11];
    const float* gamma = (const float*)d_in[12];
    const float* beta  = (const float*)d_in[13];
    float* out = (float*)d_out;

    float *p_stats;
    int *p_deg;
    cudaGetSymbolAddress((void**)&p_stats, g_stats);
    cudaGetSymbolAddress((void**)&p_deg, g_deg);

    static cudaStream_t s2 = nullptr;
    static cudaEvent_t evFork = nullptr, evJoin = nullptr;
    static bool attrSet = false;
    if (!s2) {
        cudaStreamCreateWithFlags(&s2, cudaStreamNonBlocking);
        cudaEventCreateWithFlags(&evFork, cudaEventDisableTiming);
        cudaEventCreateWithFlags(&evJoin, cudaEventDisableTiming);
    }
    if (!attrSet) {
        cudaFuncSetAttribute(gemm2_tc, cudaFuncAttributeMaxDynamicSharedMemorySize,
                             2 * 128 * LDH * (int)sizeof(__half));
        attrSet = true;
    }

    // ---- fork: edge/CSR pipeline on s2, node/GEMM pipeline on default ----
    cudaEventRecord(evFork, 0);
    cudaStreamWaitEvent(s2, evFork, 0);

    cudaMemsetAsync(p_deg, 0, NN * sizeof(int), s2);
    hist<<<(EE + 255) / 256, 256, 0, s2>>>(ei);
    scan_local<<<SCAN_BLOCKS, 256, 0, s2>>>();
    scan_bsums<<<1, 256, 0, s2>>>();
    scan_add<<<SCAN_BLOCKS, 256, 0, s2>>>();
    edge_gauss_scatter<<<(EE * 16 + 255) / 256, 256, 0, s2>>>(ea, Wsh, bsh, ei);
    cudaEventRecord(evJoin, s2);

    cudaMemsetAsync(p_stats, 0, 2 * CC * sizeof(float));
    prep_wcat<<<(512 * 128 + 255) / 256, 256>>>(Wf, Ws);
    gemm1<<<(NN + 127) / 128, 256>>>(h, W0, b0, NN);
    gemm2_tc<<<dim3((NN + 127) / 128, 4), 256, 2 * 128 * LDH * sizeof(__half)>>>();

    cudaStreamWaitEvent(0, evJoin, 0);

    const int blocks = 1024;
    edge_msg_csr<<<blocks, 256>>>(Wf, Ws, bf, bs, blocks * 8);
    finalize<<<(NN * 32 + 255) / 256, 256>>>(gamma, beta, out);
}